// round 4
// baseline (speedup 1.0000x reference)
#include <cuda_runtime.h>
#include <cuda_bf16.h>

// Problem constants
#define BB 4
#define PP 64
#define SS 8
#define YD 16
#define GD 48
#define NOUT (BB*PP*PP*SS*SS)          // 1,048,576 outputs

#define WARPS_PER_BLOCK 8

__device__ __forceinline__ float dot4(float4 v, float4 w) {
    return fmaf(v.x, w.x, fmaf(v.y, w.y, fmaf(v.z, w.z, v.w * w.w)));
}

// ---------------------------------------------------------------------------
// Single fused kernel. Each warp: 64 consecutive outputs = the full 8x8
// (si,sj) block for one (b,i,j) = one 12KB contiguous tile of g.
//
// Broadcast terms (one prologue per 12KB instead of per 6KB):
//   c1[b,j,s] = y[b,j,s,:]·Wy[0:16] -- 8 values from one contiguous 512B row
//   of y: 1 LDG.128/lane + quad butterfly reduce + shfl.idx. c2 symmetric
//   with row (b,i), Wy[16:32]; lane needs si = lane>>3 and (lane>>3)+4.
//
// Main contraction:
//   24 coalesced LDG.128 per lane (float4 f = lane + 32k, k=0..23); weight
//   column f%12 = (lane%12 + 8k)%12 cycles {A,B,C} with k%3 -> 3 register
//   float4s. Partials -> smem (conflict-free STS.32); lane r reduces rows
//   r and r+32 via 3 conflict-free LDS.128 each; 2 coalesced stores.
// ---------------------------------------------------------------------------
__global__ __launch_bounds__(32 * WARPS_PER_BLOCK)
void fused_kernel(const float* __restrict__ y,
                  const float* __restrict__ g,
                  const float* __restrict__ Wy,
                  const float* __restrict__ by,
                  const float* __restrict__ Wg,
                  const float* __restrict__ bg,
                  float* __restrict__ out) {
    __shared__ float part[WARPS_PER_BLOCK][12 * 64];

    const int lane = threadIdx.x & 31;
    const int wIn  = threadIdx.x >> 5;
    const int warp = blockIdx.x * WARPS_PER_BLOCK + wIn;
    const int base = warp * 64;

    // ---- kick off first load batch, hide prologue under it ----
    const float4* gs = (const float4*)(g + (size_t)base * GD);   // 768 float4
    float4 v0 = __ldcs(gs + lane +   0);
    float4 v1 = __ldcs(gs + lane +  32);
    float4 v2 = __ldcs(gs + lane +  64);
    float4 v3 = __ldcs(gs + lane +  96);
    float4 v4 = __ldcs(gs + lane + 128);
    float4 v5 = __ldcs(gs + lane + 160);

    // ---- broadcast terms: warp-cooperative dots over two y rows ----
    const int j = (base >> 6)  & 63;
    const int i = (base >> 12) & 63;
    const int b =  base >> 18;

    const int q = lane & 3;
    const float4 w1 = *(const float4*)(Wy + 4 * q);          // Wy[0:16] seg q
    const float4 w2 = *(const float4*)(Wy + YD + 4 * q);     // Wy[16:32] seg q
    const float4* rowj = (const float4*)(y + (size_t)((b << 6) + j) * (SS * YD));
    const float4* rowi = (const float4*)(y + (size_t)((b << 6) + i) * (SS * YD));
    float p1 = dot4(rowj[lane], w1);                         // y[b,j, l>>2, 4q..]
    float p2 = dot4(rowi[lane], w2);
    p1 += __shfl_xor_sync(0xffffffffu, p1, 1);
    p1 += __shfl_xor_sync(0xffffffffu, p1, 2);
    p2 += __shfl_xor_sync(0xffffffffu, p2, 1);
    p2 += __shfl_xor_sync(0xffffffffu, p2, 2);
    // c1[s] / c2[s] live in all lanes of quad s
    const float bias = __ldg(by) + __ldg(bg);
    const float c1  = __shfl_sync(0xffffffffu, p1, (lane & 7) << 2) + bias;
    const float c2a = __shfl_sync(0xffffffffu, p2, (lane >> 3) << 2);
    const float c2b = __shfl_sync(0xffffffffu, p2, ((lane >> 3) + 4) << 2);

    // ---- per-lane weight columns: (lane%12 + {0,8,4}) % 12 ----
    const int l12 = lane % 12;
    int cB = l12 + 8; if (cB >= 12) cB -= 12;
    int cC = l12 + 4; if (cC >= 12) cC -= 12;
    const float4* wv = (const float4*)Wg;
    const float4 wA = __ldg(wv + l12);
    const float4 wB = __ldg(wv + cB);
    const float4 wC = __ldg(wv + cC);

    float* p = part[wIn];

    // ---- batch 0 compute (k = 0..5) ----
    p[lane +   0] = dot4(v0, wA);
    p[lane +  32] = dot4(v1, wB);
    p[lane +  64] = dot4(v2, wC);
    p[lane +  96] = dot4(v3, wA);
    p[lane + 128] = dot4(v4, wB);
    p[lane + 160] = dot4(v5, wC);

    // ---- batches 1..3 (k = 6..23) ----
#pragma unroll
    for (int kb = 1; kb < 4; ++kb) {
        const int k0 = kb * 6;
        float4 u0 = __ldcs(gs + lane + 32 * (k0 + 0));
        float4 u1 = __ldcs(gs + lane + 32 * (k0 + 1));
        float4 u2 = __ldcs(gs + lane + 32 * (k0 + 2));
        float4 u3 = __ldcs(gs + lane + 32 * (k0 + 3));
        float4 u4 = __ldcs(gs + lane + 32 * (k0 + 4));
        float4 u5 = __ldcs(gs + lane + 32 * (k0 + 5));
        p[lane + 32 * (k0 + 0)] = dot4(u0, wA);
        p[lane + 32 * (k0 + 1)] = dot4(u1, wB);
        p[lane + 32 * (k0 + 2)] = dot4(u2, wC);
        p[lane + 32 * (k0 + 3)] = dot4(u3, wA);
        p[lane + 32 * (k0 + 4)] = dot4(u4, wB);
        p[lane + 32 * (k0 + 5)] = dot4(u5, wC);
    }

    __syncwarp();

    // ---- reduce: lane r owns outputs base+r and base+32+r ----
    const float4* pr0 = (const float4*)(p + lane * 12);            // row r
    const float4* pr1 = (const float4*)(p + (lane + 32) * 12);     // row r+32
    float4 a0 = pr0[0], a1 = pr0[1], a2 = pr0[2];
    float4 b0 = pr1[0], b1 = pr1[1], b2 = pr1[2];
    float s0 = ((a0.x + a0.y) + (a0.z + a0.w))
             + ((a1.x + a1.y) + (a1.z + a1.w))
             + ((a2.x + a2.y) + (a2.z + a2.w))
             + c1 + c2a;
    float s1 = ((b0.x + b0.y) + (b0.z + b0.w))
             + ((b1.x + b1.y) + (b1.z + b1.w))
             + ((b2.x + b2.y) + (b2.z + b2.w))
             + c1 + c2b;

    __stcs(out + base + lane, s0);
    __stcs(out + base + 32 + lane, s1);
}

// ---------------------------------------------------------------------------
// Launch
// inputs (metadata order): y(32768), pairwise_g(50331648), Wy(32), by(1),
//                          Wg(48), bg(1)
// ---------------------------------------------------------------------------
extern "C" void kernel_launch(void* const* d_in, const int* in_sizes, int n_in,
                              void* d_out, int out_size) {
    const float* y  = (const float*)d_in[0];
    const float* g  = (const float*)d_in[1];
    const float* Wy = (const float*)d_in[2];
    const float* by = (const float*)d_in[3];
    const float* Wg = (const float*)d_in[4];
    const float* bg = (const float*)d_in[5];
    float* out = (float*)d_out;

    const int tiles  = NOUT / 64;                 // 16384 warps
    const int blocks = tiles / WARPS_PER_BLOCK;   // 2048
    fused_kernel<<<blocks, 32 * WARPS_PER_BLOCK>>>(y, g, Wy, by, Wg, bg, out);
}

// round 5
// speedup vs baseline: 1.1223x; 1.1223x over previous
#include <cuda_runtime.h>
#include <cuda_bf16.h>

// Problem constants
#define BB 4
#define PP 64
#define SS 8
#define YD 16
#define GD 48
#define NOUT (BB*PP*PP*SS*SS)          // 1,048,576 outputs

#define WARPS_PER_BLOCK 8              // 256 threads = 256 consecutive outputs

__device__ __forceinline__ float dot4(float4 v, float4 w) {
    return fmaf(v.x, w.x, fmaf(v.y, w.y, fmaf(v.z, w.z, v.w * w.w)));
}

// ---------------------------------------------------------------------------
// Fused kernel. Block = 256 consecutive outputs: (b,i) fixed, j spans 4
// values, (si,sj) full. Threads 0..39 build the block's broadcast tables in
// smem (40 dot products over L1-resident y/Wy), one __syncthreads, then each
// warp runs the R2 streaming loop over its 6KB g tile:
//   - 2 batches x 6 coalesced LDG.128 (lane l -> float4 f = l + 32k)
//   - weight column f%12 = (l%12+8k)%12 cycles {A,B,C}: 3 register float4s
//   - per-lane partial -> smem (conflict-free STS.32)
//   - lane r sums its 12 partials via 3 conflict-free LDS.128
//   - + sc1[jj][sj] + sc2[si] from smem (broadcast LDS)
// ---------------------------------------------------------------------------
__global__ __launch_bounds__(32 * WARPS_PER_BLOCK)
void fused_kernel(const float* __restrict__ y,
                  const float* __restrict__ g,
                  const float* __restrict__ Wy,
                  const float* __restrict__ by,
                  const float* __restrict__ Wg,
                  const float* __restrict__ bg,
                  float* __restrict__ out) {
    __shared__ float part[WARPS_PER_BLOCK][12 * 32];
    __shared__ float sc1[4 * SS];      // c1[jj][s] (+bias)
    __shared__ float sc2[SS];          // c2[s]

    const int tid  = threadIdx.x;
    const int lane = tid & 31;
    const int wIn  = tid >> 5;
    const int blockBase = blockIdx.x * 256;

    // ---- per-block broadcast tables (threads 0..39 only) ----
    if (tid < 40) {
        const int b  =  blockBase >> 18;
        const int i  = (blockBase >> 12) & 63;
        const int j0 = (blockBase >> 6)  & 63;       // low 2 bits are 0
        int row, woff;
        if (tid < 32) {                              // sc1: jj = tid>>3, s = tid&7
            row  = ((b << 6) + j0 + (tid >> 3)) * SS + (tid & 7);
            woff = 0;
        } else {                                     // sc2: s = tid-32
            row  = ((b << 6) + i) * SS + (tid - 32);
            woff = YD;
        }
        const float4* yr = (const float4*)(y + (size_t)row * YD);
        const float4* wr = (const float4*)(Wy + woff);
        float d = dot4(yr[0], wr[0]) + dot4(yr[1], wr[1])
                + dot4(yr[2], wr[2]) + dot4(yr[3], wr[3]);
        if (tid < 32) sc1[tid] = d + __ldg(by) + __ldg(bg);
        else          sc2[tid - 32] = d;
    }

    // ---- per-lane weight columns: (lane%12 + {0,8,4}) % 12 ----
    const int l12 = lane % 12;
    int cB = l12 + 8; if (cB >= 12) cB -= 12;
    int cC = l12 + 4; if (cC >= 12) cC -= 12;
    const float4* wv = (const float4*)Wg;
    const float4 wA = __ldg(wv + l12);
    const float4 wB = __ldg(wv + cB);
    const float4 wC = __ldg(wv + cC);

    // ---- batch 1 loads (6 in flight) ----
    const int base = blockBase + wIn * 32;
    const float4* gs = (const float4*)(g + (size_t)base * GD);
    float4 v0 = __ldcs(gs + lane +   0);
    float4 v1 = __ldcs(gs + lane +  32);
    float4 v2 = __ldcs(gs + lane +  64);
    float4 v3 = __ldcs(gs + lane +  96);
    float4 v4 = __ldcs(gs + lane + 128);
    float4 v5 = __ldcs(gs + lane + 160);

    __syncthreads();                    // tables ready (loads stay in flight)

    float* p = part[wIn];
    p[lane +   0] = dot4(v0, wA);
    p[lane +  32] = dot4(v1, wB);
    p[lane +  64] = dot4(v2, wC);
    p[lane +  96] = dot4(v3, wA);
    p[lane + 128] = dot4(v4, wB);
    p[lane + 160] = dot4(v5, wC);

    // ---- batch 2 ----
    float4 u0 = __ldcs(gs + lane + 192);
    float4 u1 = __ldcs(gs + lane + 224);
    float4 u2 = __ldcs(gs + lane + 256);
    float4 u3 = __ldcs(gs + lane + 288);
    float4 u4 = __ldcs(gs + lane + 320);
    float4 u5 = __ldcs(gs + lane + 352);
    p[lane + 192] = dot4(u0, wA);
    p[lane + 224] = dot4(u1, wB);
    p[lane + 256] = dot4(u2, wC);
    p[lane + 288] = dot4(u3, wA);
    p[lane + 320] = dot4(u4, wB);
    p[lane + 352] = dot4(u5, wC);

    __syncwarp();

    // ---- reduce: lane r owns output base+r ----
    const float4* pr = (const float4*)(p + lane * 12);   // 48B aligned
    float4 t0 = pr[0], t1 = pr[1], t2 = pr[2];
    float sum = ((t0.x + t0.y) + (t0.z + t0.w))
              + ((t1.x + t1.y) + (t1.z + t1.w))
              + ((t2.x + t2.y) + (t2.z + t2.w));

    // broadcast terms: warp's jj = wIn>>1, si0 = (wIn&1)*4
    sum += sc1[((wIn >> 1) << 3) + (lane & 7)];
    sum += sc2[((wIn & 1) << 2) + (lane >> 3)];

    __stcs(out + base + lane, sum);
}

// ---------------------------------------------------------------------------
// Launch
// inputs (metadata order): y(32768), pairwise_g(50331648), Wy(32), by(1),
//                          Wg(48), bg(1)
// ---------------------------------------------------------------------------
extern "C" void kernel_launch(void* const* d_in, const int* in_sizes, int n_in,
                              void* d_out, int out_size) {
    const float* y  = (const float*)d_in[0];
    const float* g  = (const float*)d_in[1];
    const float* Wy = (const float*)d_in[2];
    const float* by = (const float*)d_in[3];
    const float* Wg = (const float*)d_in[4];
    const float* bg = (const float*)d_in[5];
    float* out = (float*)d_out;

    const int blocks = NOUT / 256;                // 4096
    fused_kernel<<<blocks, 32 * WARPS_PER_BLOCK>>>(y, g, Wy, by, Wg, bg, out);
}